// round 8
// baseline (speedup 1.0000x reference)
#include <cuda_runtime.h>

#define BB 8
#define CC 32
#define HH 384
#define WW 768
#define NPIX (BB * HH * WW)          // 2359296
#define CHW  ((size_t)CC * HH * WW)
#define HW   ((size_t)HH * WW)
#define NBLK 888                     // 148 SMs x 6 resident blocks @ regs<=40
#define NTILE (NPIX / 256)           // 9216 tiles of 256 pixels

__global__ __launch_bounds__(256)
void disparity_warp_k8(const float* __restrict__ src,
                       const float* __restrict__ disp,
                       float* __restrict__ out) {
    for (int tile = blockIdx.x; tile < NTILE; tile += NBLK) {
        const int idx = tile * 256 + threadIdx.x;

        const int w = idx % WW;
        const int t = idx / WW;
        const int h = t % HH;
        const int b = t / HH;

        const float d = disp[idx];
        const float ix = ((float)w - d) * (768.0f / 767.0f) - 0.5f;
        const float iy = (float)h * (384.0f / 383.0f) - 0.5f;

        const float x0f = floorf(ix);
        const float y0f = floorf(iy);
        const float fx = ix - x0f;
        const float fy = iy - y0f;
        const int x0 = (int)x0f, y0 = (int)y0f;
        const int x1 = x0 + 1,  y1 = y0 + 1;

        // zero-padding: fold OOB mask into weights, clamp indices for loads
        const bool xi0 = (x0 >= 0) & (x0 < WW);
        const bool xi1 = (x1 >= 0) & (x1 < WW);
        const bool yi0 = (y0 >= 0) & (y0 < HH);
        const bool yi1 = (y1 >= 0) & (y1 < HH);

        const float w00 = (1.0f - fy) * (1.0f - fx) * (float)(xi0 & yi0);
        const float w01 = (1.0f - fy) * fx          * (float)(xi1 & yi0);
        const float w10 = fy * (1.0f - fx)          * (float)(xi0 & yi1);
        const float w11 = fy * fx                   * (float)(xi1 & yi1);

        const int cx0 = min(max(x0, 0), WW - 1);
        const int cx1 = min(max(x1, 0), WW - 1);
        const int cy0 = min(max(y0, 0), HH - 1);
        const int cy1 = min(max(y1, 0), HH - 1);

        const int o00 = cy0 * WW + cx0;
        const int o01 = cy0 * WW + cx1;
        const int o10 = cy1 * WW + cx0;
        const int o11 = cy1 * WW + cx1;

        const float* sb = src + (size_t)b * CHW;
        float* ob = out + (size_t)b * CHW + (size_t)h * WW + w;

        #pragma unroll 8
        for (int c = 0; c < CC; ++c) {
            const float* p = sb + (size_t)c * HW;
            const float v = p[o00] * w00 + p[o01] * w01
                          + p[o10] * w10 + p[o11] * w11;
            __stcs(ob + (size_t)c * HW, v);   // streaming store: out never re-read
        }
    }
}

extern "C" void kernel_launch(void* const* d_in, const int* in_sizes, int n_in,
                              void* d_out, int out_size) {
    const float* src  = (const float*)d_in[0];
    const float* disp = (const float*)d_in[1];
    float* out = (float*)d_out;

    disparity_warp_k8<<<NBLK, 256>>>(src, disp, out);
}

// round 9
// speedup vs baseline: 1.1424x; 1.1424x over previous
#include <cuda_runtime.h>

#define BB 8
#define CC 32
#define HH 384
#define WW 768
#define HW  (HH * WW)
#define CHW ((size_t)CC * HH * WW)
#define CPI 4                        // channels per iteration

__global__ __launch_bounds__(768)
void disparity_warp_k9(const float* __restrict__ src,
                       const float* __restrict__ disp,
                       float* __restrict__ out) {
    __shared__ float tmp[2][CPI][WW];   // double-buffered vert-interpolated rows

    const int w = threadIdx.x;          // 0..767
    const int h = blockIdx.x % HH;
    const int b = blockIdx.x / HH;

    // ---- vertical coords: uniform per block ----
    const float iy  = (float)h * (384.0f / 383.0f) - 0.5f;
    const float y0f = floorf(iy);
    const float fy  = iy - y0f;
    const int   y0  = (int)y0f, y1 = y0 + 1;
    const float wy0 = (1.0f - fy) * (((y0 >= 0) & (y0 < HH)) ? 1.0f : 0.0f);
    const float wy1 = fy          * (((y1 >= 0) & (y1 < HH)) ? 1.0f : 0.0f);
    const int   cy0 = min(max(y0, 0), HH - 1);
    const int   cy1 = min(max(y1, 0), HH - 1);

    // ---- horizontal coords: per-thread ----
    const float d   = disp[(b * HH + h) * WW + w];
    const float ix  = ((float)w - d) * (768.0f / 767.0f) - 0.5f;
    const float x0f = floorf(ix);
    const float fx  = ix - x0f;
    const int   x0  = (int)x0f, x1 = x0 + 1;
    const float wx0 = (1.0f - fx) * (((x0 >= 0) & (x0 < WW)) ? 1.0f : 0.0f);
    const float wx1 = fx          * (((x1 >= 0) & (x1 < WW)) ? 1.0f : 0.0f);
    const int   cx0 = min(max(x0, 0), WW - 1);
    const int   cx1 = min(max(x1, 0), WW - 1);

    const float* r0 = src + (size_t)b * CHW + (size_t)cy0 * WW + w;  // coalesced
    const float* r1 = src + (size_t)b * CHW + (size_t)cy1 * WW + w;  // coalesced
    float* ob = out + (size_t)b * CHW + (size_t)h * WW + w;

    #pragma unroll
    for (int it = 0; it < CC / CPI; ++it) {
        const int buf = it & 1;

        // phase 1: vertical interp, fully coalesced (8 LDG in flight)
        float v[CPI];
        #pragma unroll
        for (int cc = 0; cc < CPI; ++cc) {
            const int c = it * CPI + cc;
            const float a0 = r0[(size_t)c * HW];
            const float a1 = r1[(size_t)c * HW];
            v[cc] = a0 * wy0 + a1 * wy1;
        }
        #pragma unroll
        for (int cc = 0; cc < CPI; ++cc)
            tmp[buf][cc][w] = v[cc];

        __syncthreads();

        // phase 2: horizontal interp from shared row, coalesced store
        #pragma unroll
        for (int cc = 0; cc < CPI; ++cc) {
            const int c = it * CPI + cc;
            const float t = tmp[buf][cc][cx0] * wx0 + tmp[buf][cc][cx1] * wx1;
            ob[(size_t)c * HW] = t;
        }
        // no second barrier: next iteration writes the other buffer;
        // buffer reuse is separated by the next iteration's __syncthreads.
    }
}

extern "C" void kernel_launch(void* const* d_in, const int* in_sizes, int n_in,
                              void* d_out, int out_size) {
    const float* src  = (const float*)d_in[0];
    const float* disp = (const float*)d_in[1];
    float* out = (float*)d_out;

    disparity_warp_k9<<<BB * HH, 768>>>(src, disp, out);
}